// round 1
// baseline (speedup 1.0000x reference)
#include <cuda_runtime.h>
#include <cuda_bf16.h>

#define N_ROWS 8192
#define D_IN   768
#define D_HID  16384
#define TOPK   32

// ---------------- scratch (static device globals: allocation-free) ----------
__device__ float g_Wt[(size_t)D_HID * D_IN];     // W_dec^T  [D_HID, D_IN], 48 MB
__device__ float g_vals[N_ROWS * TOPK];          // top-k values per row
__device__ int   g_idx [N_ROWS * TOPK];          // top-k indices per row

// ---------------- encoder GEMM: C = relu(x @ W_enc^T) ----------------------
// A = x [N_ROWS, D_IN] row-major, B = W_enc [D_HID, D_IN] row-major (NT GEMM).
#define BM 128
#define BN 128
#define BK 8
#define TM 8
#define TN 8

__global__ __launch_bounds__(256, 2)
void enc_gemm_kernel(const float* __restrict__ A, const float* __restrict__ B,
                     float* __restrict__ C) {
    __shared__ float As[BK][BM];
    __shared__ float Bs[BK][BN];

    const int bm  = blockIdx.y * BM;
    const int bn  = blockIdx.x * BN;
    const int tid = threadIdx.x;
    const int tx  = tid & 15;          // 16 cols of threads
    const int ty  = tid >> 4;          // 16 rows of threads
    const int lrow = tid >> 1;         // 0..127 (load row)
    const int lcol = (tid & 1) * 4;    // 0 or 4 (load col within BK)

    const float* Aptr = A + (size_t)(bm + lrow) * D_IN + lcol;
    const float* Bptr = B + (size_t)(bn + lrow) * D_IN + lcol;

    float acc[TM][TN];
    #pragma unroll
    for (int i = 0; i < TM; i++)
        #pragma unroll
        for (int j = 0; j < TN; j++) acc[i][j] = 0.0f;

    for (int k0 = 0; k0 < D_IN; k0 += BK) {
        float4 a4 = *reinterpret_cast<const float4*>(Aptr + k0);
        float4 b4 = *reinterpret_cast<const float4*>(Bptr + k0);
        As[lcol + 0][lrow] = a4.x;
        As[lcol + 1][lrow] = a4.y;
        As[lcol + 2][lrow] = a4.z;
        As[lcol + 3][lrow] = a4.w;
        Bs[lcol + 0][lrow] = b4.x;
        Bs[lcol + 1][lrow] = b4.y;
        Bs[lcol + 2][lrow] = b4.z;
        Bs[lcol + 3][lrow] = b4.w;
        __syncthreads();

        #pragma unroll
        for (int kk = 0; kk < BK; kk++) {
            float4 ra0 = *reinterpret_cast<const float4*>(&As[kk][ty * TM]);
            float4 ra1 = *reinterpret_cast<const float4*>(&As[kk][ty * TM + 4]);
            float4 rb0 = *reinterpret_cast<const float4*>(&Bs[kk][tx * TN]);
            float4 rb1 = *reinterpret_cast<const float4*>(&Bs[kk][tx * TN + 4]);
            float ra[TM] = {ra0.x, ra0.y, ra0.z, ra0.w, ra1.x, ra1.y, ra1.z, ra1.w};
            float rb[TN] = {rb0.x, rb0.y, rb0.z, rb0.w, rb1.x, rb1.y, rb1.z, rb1.w};
            #pragma unroll
            for (int i = 0; i < TM; i++)
                #pragma unroll
                for (int j = 0; j < TN; j++)
                    acc[i][j] = fmaf(ra[i], rb[j], acc[i][j]);
        }
        __syncthreads();
    }

    // epilogue: ReLU + store
    #pragma unroll
    for (int i = 0; i < TM; i++) {
        float4 o0, o1;
        o0.x = fmaxf(acc[i][0], 0.0f);
        o0.y = fmaxf(acc[i][1], 0.0f);
        o0.z = fmaxf(acc[i][2], 0.0f);
        o0.w = fmaxf(acc[i][3], 0.0f);
        o1.x = fmaxf(acc[i][4], 0.0f);
        o1.y = fmaxf(acc[i][5], 0.0f);
        o1.z = fmaxf(acc[i][6], 0.0f);
        o1.w = fmaxf(acc[i][7], 0.0f);
        size_t off = (size_t)(bm + ty * TM + i) * D_HID + bn + tx * TN;
        *reinterpret_cast<float4*>(C + off)     = o0;
        *reinterpret_cast<float4*>(C + off + 4) = o1;
    }
}

// ---------------- exact top-K per row (bit bisection) -----------------------
// Values are post-ReLU (>= 0), so the uint bit pattern is order-preserving.
__global__ __launch_bounds__(512)
void topk_kernel(float* __restrict__ latent) {
    const int row = blockIdx.x;
    const int tid = threadIdx.x;
    float* rp = latent + (size_t)row * D_HID;

    unsigned v[32];
    #pragma unroll
    for (int i = 0; i < 32; i++)
        v[i] = __float_as_uint(rp[tid + i * 512]);

    __shared__ int s_cnt;

    // binary search for the bit pattern of the K-th largest value
    unsigned lo = 0u, hi = 0xFFFFFFFFu;
    while (lo < hi) {
        unsigned mid = lo + ((hi - lo) >> 1);
        if (tid == 0) s_cnt = 0;
        __syncthreads();
        int c = 0;
        #pragma unroll
        for (int i = 0; i < 32; i++) c += (v[i] > mid) ? 1 : 0;
        #pragma unroll
        for (int o = 16; o > 0; o >>= 1) c += __shfl_down_sync(0xffffffffu, c, o);
        if ((tid & 31) == 0 && c) atomicAdd(&s_cnt, c);
        __syncthreads();
        int total = s_cnt;
        if (total >= TOPK) lo = mid + 1; else hi = mid;
        __syncthreads();   // protect s_cnt before next-iter reset
    }
    const unsigned thresh = lo;   // bit pattern of K-th largest value

    // count strictly-greater to know how many equals to admit
    if (tid == 0) s_cnt = 0;
    __syncthreads();
    {
        int c = 0;
        #pragma unroll
        for (int i = 0; i < 32; i++) c += (v[i] > thresh) ? 1 : 0;
        #pragma unroll
        for (int o = 16; o > 0; o >>= 1) c += __shfl_down_sync(0xffffffffu, c, o);
        if ((tid & 31) == 0 && c) atomicAdd(&s_cnt, c);
    }
    __syncthreads();
    const int total_gt = s_cnt;
    const int need_eq  = TOPK - total_gt;

    __shared__ int s_eq, s_slot;
    if (tid == 0) { s_eq = 0; s_slot = 0; }
    __syncthreads();

    #pragma unroll
    for (int i = 0; i < 32; i++) {
        unsigned b = v[i];
        bool sel = (b > thresh);
        if (!sel && b == thresh) {
            int p = atomicAdd(&s_eq, 1);
            sel = (p < need_eq);
        }
        int   col = tid + i * 512;
        float val = __uint_as_float(b);
        rp[col] = sel ? val : 0.0f;
        if (sel) {
            int slot = atomicAdd(&s_slot, 1);
            g_vals[row * TOPK + slot] = val;
            g_idx [row * TOPK + slot] = col;
        }
    }
}

// ---------------- W_dec transpose: [D_IN, D_HID] -> [D_HID, D_IN] -----------
__global__ void transpose_kernel(const float* __restrict__ Wdec) {
    __shared__ float tile[32][33];
    const int h0 = blockIdx.x * 32;
    const int d0 = blockIdx.y * 32;
    const int x = threadIdx.x, y = threadIdx.y;   // block (32, 8)
    #pragma unroll
    for (int i = 0; i < 32; i += 8)
        tile[y + i][x] = Wdec[(size_t)(d0 + y + i) * D_HID + h0 + x];
    __syncthreads();
    #pragma unroll
    for (int i = 0; i < 32; i += 8)
        g_Wt[(size_t)(h0 + y + i) * D_IN + d0 + x] = tile[x][y + i];
}

// ---------------- sparse decoder: recon = latent_sparse @ W_dec^T -----------
__global__ __launch_bounds__(256)
void decode_kernel(float* __restrict__ recon) {
    const int row = blockIdx.x;
    const int tid = threadIdx.x;
    __shared__ float sv[TOPK];
    __shared__ int   si[TOPK];
    if (tid < TOPK) {
        sv[tid] = g_vals[row * TOPK + tid];
        si[tid] = g_idx [row * TOPK + tid];
    }
    __syncthreads();

    float a0 = 0.0f, a1 = 0.0f, a2 = 0.0f;
    #pragma unroll
    for (int j = 0; j < TOPK; j++) {
        const float* wr = g_Wt + (size_t)si[j] * D_IN;
        float s = sv[j];
        a0 = fmaf(s, wr[tid],       a0);
        a1 = fmaf(s, wr[tid + 256], a1);
        a2 = fmaf(s, wr[tid + 512], a2);
    }
    size_t off = (size_t)row * D_IN + tid;
    recon[off]       = a0;
    recon[off + 256] = a1;
    recon[off + 512] = a2;
}

// ---------------- launch -----------------------------------------------------
extern "C" void kernel_launch(void* const* d_in, const int* in_sizes, int n_in,
                              void* d_out, int out_size) {
    const float* x    = (const float*)d_in[0];   // [8192, 768]
    const float* Wenc = (const float*)d_in[1];   // [16384, 768]
    const float* Wdec = (const float*)d_in[2];   // [768, 16384]

    float* out    = (float*)d_out;
    float* latent = out;                                  // [8192, 16384]
    float* recon  = out + (size_t)N_ROWS * D_HID;         // [8192, 768]

    transpose_kernel<<<dim3(D_HID / 32, D_IN / 32), dim3(32, 8)>>>(Wdec);
    enc_gemm_kernel<<<dim3(D_HID / BN, N_ROWS / BM), 256>>>(x, Wenc, latent);
    topk_kernel<<<N_ROWS, 512>>>(latent);
    decode_kernel<<<N_ROWS, 256>>>(recon);
}

// round 3
// speedup vs baseline: 3.4908x; 3.4908x over previous
#include <cuda_runtime.h>
#include <cuda_bf16.h>
#include <cstdint>

#define N_ROWS 8192
#define D_IN   768
#define D_HID  16384
#define TOPK   32
#define TOPC   48

// ---------------- scratch (static device globals: allocation-free) ----------
__device__ float          g_Wt[(size_t)D_HID * D_IN];     // W_dec^T, 48 MB
__device__ __nv_bfloat16  g_xb[(size_t)N_ROWS * D_IN];    // x in bf16
__device__ __nv_bfloat16  g_wb[(size_t)D_HID * D_IN];     // W_enc in bf16
__device__ int            g_cidx[N_ROWS * TOPC];          // candidate columns
__device__ float          g_vals[N_ROWS * TOPK];          // final top-k values (rank order)
__device__ int            g_idx [N_ROWS * TOPK];          // final top-k columns (rank order)

// ======================= helpers ============================================
__device__ __forceinline__ uint32_t smem_u32(const void* p) {
    uint32_t a;
    asm("{ .reg .u64 t; cvta.to.shared.u64 t, %1; cvt.u32.u64 %0, t; }" : "=r"(a) : "l"(p));
    return a;
}
__device__ __forceinline__ void cp16(uint32_t saddr, const void* gaddr) {
    asm volatile("cp.async.cg.shared.global [%0], [%1], 16;\n" :: "r"(saddr), "l"(gaddr));
}
__device__ __forceinline__ void ldmatrix_x4(uint32_t& r0, uint32_t& r1, uint32_t& r2,
                                            uint32_t& r3, uint32_t addr) {
    asm volatile("ldmatrix.sync.aligned.m8n8.x4.shared.b16 {%0,%1,%2,%3}, [%4];"
                 : "=r"(r0), "=r"(r1), "=r"(r2), "=r"(r3) : "r"(addr));
}
__device__ __forceinline__ void mma_bf16(float* c, const uint32_t* a, const uint32_t* b) {
    asm volatile(
        "mma.sync.aligned.m16n8k16.row.col.f32.bf16.bf16.f32 "
        "{%0,%1,%2,%3}, {%4,%5,%6,%7}, {%8,%9}, {%0,%1,%2,%3};"
        : "+f"(c[0]), "+f"(c[1]), "+f"(c[2]), "+f"(c[3])
        : "r"(a[0]), "r"(a[1]), "r"(a[2]), "r"(a[3]), "r"(b[0]), "r"(b[1]));
}

// ---------------- fp32 -> bf16 conversion (8 elems / thread) ----------------
__global__ void convert_x_kernel(const float* __restrict__ src) {
    int i = blockIdx.x * blockDim.x + threadIdx.x;
    const float4* s = reinterpret_cast<const float4*>(src) + (size_t)i * 2;
    float4 a = s[0], b = s[1];
    __nv_bfloat162 r[4];
    r[0] = __float22bfloat162_rn(make_float2(a.x, a.y));
    r[1] = __float22bfloat162_rn(make_float2(a.z, a.w));
    r[2] = __float22bfloat162_rn(make_float2(b.x, b.y));
    r[3] = __float22bfloat162_rn(make_float2(b.z, b.w));
    *reinterpret_cast<uint4*>(&g_xb[(size_t)i * 8]) = *reinterpret_cast<uint4*>(r);
}
__global__ void convert_w_kernel(const float* __restrict__ src) {
    int i = blockIdx.x * blockDim.x + threadIdx.x;
    const float4* s = reinterpret_cast<const float4*>(src) + (size_t)i * 2;
    float4 a = s[0], b = s[1];
    __nv_bfloat162 r[4];
    r[0] = __float22bfloat162_rn(make_float2(a.x, a.y));
    r[1] = __float22bfloat162_rn(make_float2(a.z, a.w));
    r[2] = __float22bfloat162_rn(make_float2(b.x, b.y));
    r[3] = __float22bfloat162_rn(make_float2(b.z, b.w));
    *reinterpret_cast<uint4*>(&g_wb[(size_t)i * 8]) = *reinterpret_cast<uint4*>(r);
}

// ================= bf16 HMMA screening GEMM ================================
// scores = relu(x_bf16 @ W_enc_bf16^T), fp32 out.
// Block tile 128x128x32, 8 warps (2m x 4n), warp tile 64x32, mma.m16n8k16.
#define GBM 128
#define GBN 128
#define GBK 32
#define NCHUNK (D_IN / GBK)        // 24
#define SM_STRIDE 40               // bf16 elems per smem row (32 + 8 pad) = 80 B

__global__ __launch_bounds__(256, 2)
void screen_gemm_kernel(float* __restrict__ scores) {
    __shared__ __nv_bfloat16 As[2][GBM * SM_STRIDE];
    __shared__ __nv_bfloat16 Bs[2][GBM * SM_STRIDE];

    const int tid = threadIdx.x, wid = tid >> 5, lane = tid & 31;
    const int bm = blockIdx.y * GBM, bn = blockIdx.x * GBN;
    const int warp_m = wid >> 2;          // 0..1  -> 64 rows
    const int warp_n = wid & 3;           // 0..3  -> 32 cols

    // cp.async addressing: vec v -> row = v>>2, 16B-chunk = v&3
    const int lrow0 = tid >> 2;           // rows tid/4 and tid/4+64
    const int lc16  = tid & 3;
    const uint32_t sA[2] = { smem_u32(&As[0][0]), smem_u32(&As[1][0]) };
    const uint32_t sB[2] = { smem_u32(&Bs[0][0]), smem_u32(&Bs[1][0]) };

    auto load_chunk = [&](int buf, int kc) {
        #pragma unroll
        for (int i = 0; i < 2; i++) {
            int r = lrow0 + i * 64;
            uint32_t so = (uint32_t)(r * SM_STRIDE * 2 + lc16 * 16);
            cp16(sA[buf] + so, g_xb + (size_t)(bm + r) * D_IN + kc + lc16 * 8);
            cp16(sB[buf] + so, g_wb + (size_t)(bn + r) * D_IN + kc + lc16 * 8);
        }
    };

    // ldmatrix per-lane base offsets (bytes)
    // A m-tile: row = warp_m*64 + mt*16 + (lane&15), col = ks*16 + (lane>>4)*8
    const uint32_t a_lane_off =
        (uint32_t)(((warp_m * 64) + (lane & 15)) * SM_STRIDE + (lane >> 4) * 8) * 2;
    // B n-tile16: row = warp_n*32 + nt16*16 + ((lane>>4)<<3) + (lane&7),
    //             col = ks*16 + ((lane>>3)&1)*8
    const uint32_t b_lane_off =
        (uint32_t)(((warp_n * 32) + ((lane >> 4) << 3) + (lane & 7)) * SM_STRIDE
                   + ((lane >> 3) & 1) * 8) * 2;

    float acc[4][4][4];
    #pragma unroll
    for (int i = 0; i < 4; i++)
        #pragma unroll
        for (int j = 0; j < 4; j++)
            #pragma unroll
            for (int q = 0; q < 4; q++) acc[i][j][q] = 0.0f;

    load_chunk(0, 0);
    asm volatile("cp.async.commit_group;\n" ::: "memory");

    for (int k = 0; k < NCHUNK; k++) {
        if (k + 1 < NCHUNK) {
            load_chunk((k + 1) & 1, (k + 1) * GBK);
            asm volatile("cp.async.commit_group;\n" ::: "memory");
            asm volatile("cp.async.wait_group 1;\n" ::: "memory");
        } else {
            asm volatile("cp.async.wait_group 0;\n" ::: "memory");
        }
        __syncthreads();

        const uint32_t aB = sA[k & 1] + a_lane_off;
        const uint32_t bB = sB[k & 1] + b_lane_off;
        #pragma unroll
        for (int ks = 0; ks < 2; ks++) {
            uint32_t af[4][4], bf[2][4];
            #pragma unroll
            for (int mt = 0; mt < 4; mt++)
                ldmatrix_x4(af[mt][0], af[mt][1], af[mt][2], af[mt][3],
                            aB + (uint32_t)(mt * 16 * SM_STRIDE + ks * 16) * 2);
            #pragma unroll
            for (int nt = 0; nt < 2; nt++)
                ldmatrix_x4(bf[nt][0], bf[nt][1], bf[nt][2], bf[nt][3],
                            bB + (uint32_t)(nt * 16 * SM_STRIDE + ks * 16) * 2);
            #pragma unroll
            for (int mt = 0; mt < 4; mt++)
                #pragma unroll
                for (int nt = 0; nt < 4; nt++)
                    mma_bf16(acc[mt][nt], af[mt], &bf[nt >> 1][(nt & 1) * 2]);
        }
        __syncthreads();
    }

    // epilogue: ReLU + fp32 store
    #pragma unroll
    for (int mt = 0; mt < 4; mt++) {
        int r0 = bm + warp_m * 64 + mt * 16 + (lane >> 2);
        #pragma unroll
        for (int nt = 0; nt < 4; nt++) {
            int col = bn + warp_n * 32 + nt * 8 + (lane & 3) * 2;
            float2 lo, hi;
            lo.x = fmaxf(acc[mt][nt][0], 0.0f);
            lo.y = fmaxf(acc[mt][nt][1], 0.0f);
            hi.x = fmaxf(acc[mt][nt][2], 0.0f);
            hi.y = fmaxf(acc[mt][nt][3], 0.0f);
            *reinterpret_cast<float2*>(scores + (size_t)r0 * D_HID + col)       = lo;
            *reinterpret_cast<float2*>(scores + (size_t)(r0 + 8) * D_HID + col) = hi;
        }
    }
}

// ============ candidate selection: top-TOPC per row by screened score =======
__global__ __launch_bounds__(512)
void candidate_kernel(float* __restrict__ latent) {
    const int row = blockIdx.x;
    const int tid = threadIdx.x;
    float* rp = latent + (size_t)row * D_HID;

    unsigned v[32];
    #pragma unroll
    for (int i = 0; i < 32; i++)
        v[i] = __float_as_uint(rp[tid + i * 512]);

    __shared__ int s_cnt;
    unsigned lo = 0u, hi = 0xFFFFFFFFu;
    while (lo < hi) {
        unsigned mid = lo + ((hi - lo) >> 1);
        if (tid == 0) s_cnt = 0;
        __syncthreads();
        int c = 0;
        #pragma unroll
        for (int i = 0; i < 32; i++) c += (v[i] > mid) ? 1 : 0;
        #pragma unroll
        for (int o = 16; o > 0; o >>= 1) c += __shfl_down_sync(0xffffffffu, c, o);
        if ((tid & 31) == 0 && c) atomicAdd(&s_cnt, c);
        __syncthreads();
        int total = s_cnt;
        if (total >= TOPC) lo = mid + 1; else hi = mid;
        __syncthreads();
    }
    const unsigned thresh = lo;

    if (tid == 0) s_cnt = 0;
    __syncthreads();
    {
        int c = 0;
        #pragma unroll
        for (int i = 0; i < 32; i++) c += (v[i] > thresh) ? 1 : 0;
        #pragma unroll
        for (int o = 16; o > 0; o >>= 1) c += __shfl_down_sync(0xffffffffu, c, o);
        if ((tid & 31) == 0 && c) atomicAdd(&s_cnt, c);
    }
    __syncthreads();
    const int need_eq = TOPC - s_cnt;

    __shared__ int s_eq, s_slot;
    if (tid == 0) { s_eq = 0; s_slot = 0; }
    __syncthreads();

    #pragma unroll
    for (int i = 0; i < 32; i++) {
        unsigned b = v[i];
        bool sel = (b > thresh);
        if (!sel && b == thresh) {
            int p = atomicAdd(&s_eq, 1);
            sel = (p < need_eq);
        }
        int col = tid + i * 512;
        rp[col] = 0.0f;                              // zero entire latent row
        if (sel) {
            int slot = atomicAdd(&s_slot, 1);
            g_cidx[row * TOPC + slot] = col;
        }
    }
}

// ============ exact fp32 rescore of candidates + exact top-K ================
__global__ __launch_bounds__(256)
void rescore_kernel(const float* __restrict__ x, const float* __restrict__ Wenc,
                    float* __restrict__ latent) {
    const int row = blockIdx.x;
    const int tid = threadIdx.x, wid = tid >> 5, lid = tid & 31;
    __shared__ float s_val[TOPC];
    __shared__ int   s_col[TOPC];
    if (tid < TOPC) s_col[tid] = g_cidx[row * TOPC + tid];
    __syncthreads();

    const float* xr = x + (size_t)row * D_IN;
    for (int j = wid; j < TOPC; j += 8) {
        const float* wr = Wenc + (size_t)s_col[j] * D_IN;
        float s = 0.0f, comp = 0.0f;                 // Kahan per lane
        #pragma unroll
        for (int k = lid; k < D_IN; k += 32) {
            float p = __fmul_rn(xr[k], wr[k]);
            float y = __fsub_rn(p, comp);
            float t = __fadd_rn(s, y);
            comp = __fsub_rn(__fsub_rn(t, s), y);
            s = t;
        }
        #pragma unroll
        for (int o = 16; o > 0; o >>= 1)
            s = __fadd_rn(s, __shfl_down_sync(0xffffffffu, s, o));
        if (lid == 0) s_val[j] = fmaxf(s, 0.0f);     // ReLU
    }
    __syncthreads();

    if (tid < TOPC) {
        float v = s_val[tid];
        int   c = s_col[tid];
        int rank = 0;
        #pragma unroll 1
        for (int j = 0; j < TOPC; j++) {
            float vj = s_val[j];
            rank += ((vj > v) || (vj == v && s_col[j] < c)) ? 1 : 0;
        }
        if (rank < TOPK) {
            latent[(size_t)row * D_HID + c] = v;
            g_vals[row * TOPK + rank] = v;
            g_idx [row * TOPK + rank] = c;
        }
    }
}

// ---------------- W_dec transpose: [D_IN, D_HID] -> [D_HID, D_IN] -----------
__global__ void transpose_kernel(const float* __restrict__ Wdec) {
    __shared__ float tile[32][33];
    const int h0 = blockIdx.x * 32;
    const int d0 = blockIdx.y * 32;
    const int x = threadIdx.x, y = threadIdx.y;
    #pragma unroll
    for (int i = 0; i < 32; i += 8)
        tile[y + i][x] = Wdec[(size_t)(d0 + y + i) * D_HID + h0 + x];
    __syncthreads();
    #pragma unroll
    for (int i = 0; i < 32; i += 8)
        g_Wt[(size_t)(h0 + y + i) * D_IN + d0 + x] = tile[x][y + i];
}

// ---------------- sparse decoder: recon = latent_sparse @ W_dec^T -----------
__global__ __launch_bounds__(256)
void decode_kernel(float* __restrict__ recon) {
    const int row = blockIdx.x;
    const int tid = threadIdx.x;
    __shared__ float sv[TOPK];
    __shared__ int   si[TOPK];
    if (tid < TOPK) {
        sv[tid] = g_vals[row * TOPK + tid];
        si[tid] = g_idx [row * TOPK + tid];
    }
    __syncthreads();

    float a0 = 0.0f, a1 = 0.0f, a2 = 0.0f;
    #pragma unroll
    for (int j = 0; j < TOPK; j++) {
        const float* wr = g_Wt + (size_t)si[j] * D_IN;
        float s = sv[j];
        a0 = fmaf(s, wr[tid],       a0);
        a1 = fmaf(s, wr[tid + 256], a1);
        a2 = fmaf(s, wr[tid + 512], a2);
    }
    size_t off = (size_t)row * D_IN + tid;
    recon[off]       = a0;
    recon[off + 256] = a1;
    recon[off + 512] = a2;
}

// ---------------- launch -----------------------------------------------------
extern "C" void kernel_launch(void* const* d_in, const int* in_sizes, int n_in,
                              void* d_out, int out_size) {
    const float* x    = (const float*)d_in[0];   // [8192, 768]
    const float* Wenc = (const float*)d_in[1];   // [16384, 768]
    const float* Wdec = (const float*)d_in[2];   // [768, 16384]

    float* out    = (float*)d_out;
    float* latent = out;                                  // [8192, 16384]
    float* recon  = out + (size_t)N_ROWS * D_HID;         // [8192, 768]

    transpose_kernel<<<dim3(D_HID / 32, D_IN / 32), dim3(32, 8)>>>(Wdec);
    convert_x_kernel<<<(N_ROWS * D_IN / 8) / 256, 256>>>(x);
    convert_w_kernel<<<(D_HID * D_IN / 8) / 256, 256>>>(Wenc);
    screen_gemm_kernel<<<dim3(D_HID / GBN, N_ROWS / GBM), 256>>>(latent);
    candidate_kernel<<<N_ROWS, 512>>>(latent);
    rescore_kernel<<<N_ROWS, 256>>>(x, Wenc, latent);
    decode_kernel<<<N_ROWS, 256>>>(recon);
}

// round 4
// speedup vs baseline: 4.8348x; 1.3850x over previous
#include <cuda_runtime.h>
#include <cuda_bf16.h>
#include <cstdint>

#define N_ROWS 8192
#define D_IN   768
#define D_HID  16384
#define TOPK   32
#define TOPC   48
#define CMAX   96

// ---------------- scratch (static device globals: allocation-free) ----------
__device__ float          g_Wt[(size_t)D_HID * D_IN];     // W_dec^T, 48 MB
__device__ __nv_bfloat16  g_xb[(size_t)N_ROWS * D_IN];    // x in bf16
__device__ __nv_bfloat16  g_wb[(size_t)D_HID * D_IN];     // W_enc in bf16
__device__ __nv_bfloat16  g_sb[(size_t)N_ROWS * D_HID];   // bf16 screen scores, 268MB
__device__ int            g_cidx[(size_t)N_ROWS * CMAX];  // candidate columns
__device__ int            g_ccnt[N_ROWS];                 // candidate counts
__device__ float          g_vals[N_ROWS * TOPK];          // final top-k values (rank order)
__device__ int            g_idx [N_ROWS * TOPK];          // final top-k columns (rank order)

// ======================= helpers ============================================
__device__ __forceinline__ uint32_t smem_u32(const void* p) {
    uint32_t a;
    asm("{ .reg .u64 t; cvta.to.shared.u64 t, %1; cvt.u32.u64 %0, t; }" : "=r"(a) : "l"(p));
    return a;
}
__device__ __forceinline__ void cp16(uint32_t saddr, const void* gaddr) {
    asm volatile("cp.async.cg.shared.global [%0], [%1], 16;\n" :: "r"(saddr), "l"(gaddr));
}
__device__ __forceinline__ void ldmatrix_x4(uint32_t& r0, uint32_t& r1, uint32_t& r2,
                                            uint32_t& r3, uint32_t addr) {
    asm volatile("ldmatrix.sync.aligned.m8n8.x4.shared.b16 {%0,%1,%2,%3}, [%4];"
                 : "=r"(r0), "=r"(r1), "=r"(r2), "=r"(r3) : "r"(addr));
}
__device__ __forceinline__ void mma_bf16(float* c, const uint32_t* a, const uint32_t* b) {
    asm volatile(
        "mma.sync.aligned.m16n8k16.row.col.f32.bf16.bf16.f32 "
        "{%0,%1,%2,%3}, {%4,%5,%6,%7}, {%8,%9}, {%0,%1,%2,%3};"
        : "+f"(c[0]), "+f"(c[1]), "+f"(c[2]), "+f"(c[3])
        : "r"(a[0]), "r"(a[1]), "r"(a[2]), "r"(a[3]), "r"(b[0]), "r"(b[1]));
}

// ---------------- fp32 -> bf16 conversion (8 elems / thread) ----------------
__global__ void convert_x_kernel(const float* __restrict__ src) {
    int i = blockIdx.x * blockDim.x + threadIdx.x;
    const float4* s = reinterpret_cast<const float4*>(src) + (size_t)i * 2;
    float4 a = s[0], b = s[1];
    __nv_bfloat162 r[4];
    r[0] = __float22bfloat162_rn(make_float2(a.x, a.y));
    r[1] = __float22bfloat162_rn(make_float2(a.z, a.w));
    r[2] = __float22bfloat162_rn(make_float2(b.x, b.y));
    r[3] = __float22bfloat162_rn(make_float2(b.z, b.w));
    *reinterpret_cast<uint4*>(&g_xb[(size_t)i * 8]) = *reinterpret_cast<uint4*>(r);
}
__global__ void convert_w_kernel(const float* __restrict__ src) {
    int i = blockIdx.x * blockDim.x + threadIdx.x;
    const float4* s = reinterpret_cast<const float4*>(src) + (size_t)i * 2;
    float4 a = s[0], b = s[1];
    __nv_bfloat162 r[4];
    r[0] = __float22bfloat162_rn(make_float2(a.x, a.y));
    r[1] = __float22bfloat162_rn(make_float2(a.z, a.w));
    r[2] = __float22bfloat162_rn(make_float2(b.x, b.y));
    r[3] = __float22bfloat162_rn(make_float2(b.z, b.w));
    *reinterpret_cast<uint4*>(&g_wb[(size_t)i * 8]) = *reinterpret_cast<uint4*>(r);
}

// ================= bf16 HMMA screening GEMM ================================
// scores_bf16 = relu(x_bf16 @ W_enc_bf16^T)
// Block tile 128x128x64, 8 warps (2m x 4n), warp tile 64x32, mma.m16n8k16.
#define GBM 128
#define GBN 128
#define GBK 64
#define NCHUNK (D_IN / GBK)        // 12
#define SMS 72                     // bf16 elems per smem row (64 + 8 pad) = 144 B
#define TILE_B (GBM * SMS * 2)     // 18432 bytes per tile buffer
#define GEMM_SMEM (4 * TILE_B)     // 73728

__global__ __launch_bounds__(256, 2)
void screen_gemm_kernel(__nv_bfloat16* __restrict__ scores) {
    extern __shared__ char smem[];
    const uint32_t sbase = smem_u32(smem);
    const uint32_t sA[2] = { sbase,          sbase + 2 * TILE_B };
    const uint32_t sB[2] = { sbase + TILE_B, sbase + 3 * TILE_B };

    const int tid = threadIdx.x, wid = tid >> 5, lane = tid & 31;
    const int bm = blockIdx.y * GBM, bn = blockIdx.x * GBN;
    const int warp_m = wid >> 2;          // 0..1 -> 64 rows
    const int warp_n = wid & 3;           // 0..3 -> 32 cols

    auto load_chunk = [&](int buf, int kc) {
        #pragma unroll
        for (int i = 0; i < 4; i++) {
            int v = tid + i * 256;        // 0..1023
            int r = v >> 3, c = v & 7;
            uint32_t so = (uint32_t)(r * (SMS * 2) + c * 16);
            cp16(sA[buf] + so, g_xb + (size_t)(bm + r) * D_IN + kc + c * 8);
            cp16(sB[buf] + so, g_wb + (size_t)(bn + r) * D_IN + kc + c * 8);
        }
    };

    const uint32_t a_lane_off =
        (uint32_t)(((warp_m * 64) + (lane & 15)) * SMS + (lane >> 4) * 8) * 2;
    const uint32_t b_lane_off =
        (uint32_t)(((warp_n * 32) + ((lane >> 4) << 3) + (lane & 7)) * SMS
                   + ((lane >> 3) & 1) * 8) * 2;

    float acc[4][4][4];
    #pragma unroll
    for (int i = 0; i < 4; i++)
        #pragma unroll
        for (int j = 0; j < 4; j++)
            #pragma unroll
            for (int q = 0; q < 4; q++) acc[i][j][q] = 0.0f;

    load_chunk(0, 0);
    asm volatile("cp.async.commit_group;\n" ::: "memory");

    for (int k = 0; k < NCHUNK; k++) {
        if (k + 1 < NCHUNK) {
            load_chunk((k + 1) & 1, (k + 1) * GBK);
            asm volatile("cp.async.commit_group;\n" ::: "memory");
            asm volatile("cp.async.wait_group 1;\n" ::: "memory");
        } else {
            asm volatile("cp.async.wait_group 0;\n" ::: "memory");
        }
        __syncthreads();

        const uint32_t aB = sA[k & 1] + a_lane_off;
        const uint32_t bB = sB[k & 1] + b_lane_off;
        #pragma unroll
        for (int ks = 0; ks < 4; ks++) {
            uint32_t af[4][4], bf[2][4];
            #pragma unroll
            for (int mt = 0; mt < 4; mt++)
                ldmatrix_x4(af[mt][0], af[mt][1], af[mt][2], af[mt][3],
                            aB + (uint32_t)(mt * 16 * SMS) * 2 + (uint32_t)ks * 32);
            #pragma unroll
            for (int nt = 0; nt < 2; nt++)
                ldmatrix_x4(bf[nt][0], bf[nt][1], bf[nt][2], bf[nt][3],
                            bB + (uint32_t)(nt * 16 * SMS) * 2 + (uint32_t)ks * 32);
            #pragma unroll
            for (int mt = 0; mt < 4; mt++)
                #pragma unroll
                for (int nt = 0; nt < 4; nt++)
                    mma_bf16(acc[mt][nt], af[mt], &bf[nt >> 1][(nt & 1) * 2]);
        }
        __syncthreads();
    }

    // epilogue: ReLU + bf16 store
    #pragma unroll
    for (int mt = 0; mt < 4; mt++) {
        int r0 = bm + warp_m * 64 + mt * 16 + (lane >> 2);
        #pragma unroll
        for (int nt = 0; nt < 4; nt++) {
            int col = bn + warp_n * 32 + nt * 8 + (lane & 3) * 2;
            __nv_bfloat162 lo = __float22bfloat162_rn(
                make_float2(fmaxf(acc[mt][nt][0], 0.0f), fmaxf(acc[mt][nt][1], 0.0f)));
            __nv_bfloat162 hi = __float22bfloat162_rn(
                make_float2(fmaxf(acc[mt][nt][2], 0.0f), fmaxf(acc[mt][nt][3], 0.0f)));
            *reinterpret_cast<__nv_bfloat162*>(scores + (size_t)r0 * D_HID + col)       = lo;
            *reinterpret_cast<__nv_bfloat162*>(scores + (size_t)(r0 + 8) * D_HID + col) = hi;
        }
    }
}

// ============ candidate selection on bf16 scores + latent zeroing ===========
// Early-exit bisection on 16-bit patterns: accept any threshold with
// count(v > t) in [TOPC, CMAX]. Fallback: exact converged threshold.
__global__ __launch_bounds__(512)
void candidate_kernel(float* __restrict__ latent) {
    const int row = blockIdx.x;
    const int tid = threadIdx.x;
    const unsigned short* sp =
        reinterpret_cast<const unsigned short*>(g_sb + (size_t)row * D_HID);

    unsigned short v[32];
    #pragma unroll
    for (int i = 0; i < 4; i++) {
        uint4 q = *reinterpret_cast<const uint4*>(sp + tid * 8 + i * 4096);
        unsigned p;
        p = q.x; v[i*8+0] = (unsigned short)(p & 0xFFFF); v[i*8+1] = (unsigned short)(p >> 16);
        p = q.y; v[i*8+2] = (unsigned short)(p & 0xFFFF); v[i*8+3] = (unsigned short)(p >> 16);
        p = q.z; v[i*8+4] = (unsigned short)(p & 0xFFFF); v[i*8+5] = (unsigned short)(p >> 16);
        p = q.w; v[i*8+6] = (unsigned short)(p & 0xFFFF); v[i*8+7] = (unsigned short)(p >> 16);
    }

    __shared__ int s_cnt;
    unsigned lo = 0u, hi = 0x10000u;
    unsigned thresh = 0u;
    int mode = -1;                      // 0 = strict-greater, 1 = take-all-ge, 2 = eq-fill
    while (lo < hi) {
        unsigned mid = (lo + hi) >> 1;
        if (tid == 0) s_cnt = 0;
        __syncthreads();
        int c = 0;
        #pragma unroll
        for (int i = 0; i < 32; i++) c += ((unsigned)v[i] > mid) ? 1 : 0;
        #pragma unroll
        for (int o = 16; o > 0; o >>= 1) c += __shfl_down_sync(0xffffffffu, c, o);
        if ((tid & 31) == 0 && c) atomicAdd(&s_cnt, c);
        __syncthreads();
        int total = s_cnt;
        __syncthreads();
        if (total >= TOPC && total <= CMAX) { thresh = mid; mode = 0; break; }
        if (total >= TOPC) lo = mid + 1; else hi = mid;
    }

    int need_eq = 0;
    if (mode < 0) {                     // fallback: converged exactly, lo == hi
        thresh = lo;
        if (tid == 0) s_cnt = 0;
        __syncthreads();
        int cg = 0, ce = 0;
        #pragma unroll
        for (int i = 0; i < 32; i++) {
            cg += ((unsigned)v[i] > thresh) ? 1 : 0;
            ce += ((unsigned)v[i] == thresh) ? 1 : 0;
        }
        int both = (cg << 16) | ce;
        #pragma unroll
        for (int o = 16; o > 0; o >>= 1) both += __shfl_down_sync(0xffffffffu, both, o);
        if ((tid & 31) == 0 && both) atomicAdd(&s_cnt, both);
        __syncthreads();
        int tg = s_cnt >> 16, te = s_cnt & 0xFFFF;
        __syncthreads();
        if (tg + te <= CMAX) mode = 1;                 // take all equals too
        else { mode = 2; need_eq = TOPC - tg; }        // pathological: arbitrary eq-fill
    }

    __shared__ int s_eq, s_slot;
    if (tid == 0) { s_eq = 0; s_slot = 0; }
    __syncthreads();

    #pragma unroll
    for (int i = 0; i < 4; i++) {
        #pragma unroll
        for (int j = 0; j < 8; j++) {
            unsigned b = (unsigned)v[i * 8 + j];
            bool sel = (b > thresh);
            if (!sel && b == thresh && mode != 0) {
                if (mode == 1) sel = true;
                else { int p = atomicAdd(&s_eq, 1); sel = (p < need_eq); }
            }
            if (sel) {
                int slot = atomicAdd(&s_slot, 1);
                g_cidx[(size_t)row * CMAX + slot] = tid * 8 + i * 4096 + j;
            }
        }
    }

    // zero the full latent row (fp32 output region)
    float4 z = make_float4(0.0f, 0.0f, 0.0f, 0.0f);
    float* lp = latent + (size_t)row * D_HID;
    #pragma unroll
    for (int i = 0; i < 8; i++)
        *reinterpret_cast<float4*>(lp + tid * 4 + i * 2048) = z;

    __syncthreads();
    if (tid == 0) g_ccnt[row] = s_slot;
}

// ============ exact fp32 rescore of candidates + exact top-K ================
__global__ __launch_bounds__(256)
void rescore_kernel(const float* __restrict__ x, const float* __restrict__ Wenc,
                    float* __restrict__ latent) {
    const int row = blockIdx.x;
    const int tid = threadIdx.x, wid = tid >> 5, lid = tid & 31;
    const int C = g_ccnt[row];
    __shared__ float s_val[CMAX];
    __shared__ int   s_col[CMAX];
    if (tid < C) s_col[tid] = g_cidx[(size_t)row * CMAX + tid];
    __syncthreads();

    const float* xr = x + (size_t)row * D_IN;
    for (int j = wid; j < C; j += 8) {
        const float* wr = Wenc + (size_t)s_col[j] * D_IN;
        float s = 0.0f, comp = 0.0f;                 // Kahan per lane
        #pragma unroll
        for (int k = lid; k < D_IN; k += 32) {
            float p = __fmul_rn(xr[k], wr[k]);
            float y = __fsub_rn(p, comp);
            float t = __fadd_rn(s, y);
            comp = __fsub_rn(__fsub_rn(t, s), y);
            s = t;
        }
        #pragma unroll
        for (int o = 16; o > 0; o >>= 1)
            s = __fadd_rn(s, __shfl_down_sync(0xffffffffu, s, o));
        if (lid == 0) s_val[j] = fmaxf(s, 0.0f);     // ReLU
    }
    __syncthreads();

    if (tid < C) {
        float vv = s_val[tid];
        int   c  = s_col[tid];
        int rank = 0;
        #pragma unroll 1
        for (int j = 0; j < C; j++) {
            float vj = s_val[j];
            rank += ((vj > vv) || (vj == vv && s_col[j] < c)) ? 1 : 0;
        }
        if (rank < TOPK) {
            latent[(size_t)row * D_HID + c] = vv;
            g_vals[row * TOPK + rank] = vv;
            g_idx [row * TOPK + rank] = c;
        }
    }
}

// ---------------- W_dec transpose: [D_IN, D_HID] -> [D_HID, D_IN] -----------
__global__ void transpose_kernel(const float* __restrict__ Wdec) {
    __shared__ float tile[32][33];
    const int h0 = blockIdx.x * 32;
    const int d0 = blockIdx.y * 32;
    const int x = threadIdx.x, y = threadIdx.y;
    #pragma unroll
    for (int i = 0; i < 32; i += 8)
        tile[y + i][x] = Wdec[(size_t)(d0 + y + i) * D_HID + h0 + x];
    __syncthreads();
    #pragma unroll
    for (int i = 0; i < 32; i += 8)
        g_Wt[(size_t)(h0 + y + i) * D_IN + d0 + x] = tile[x][y + i];
}

// ---------------- sparse decoder: recon = latent_sparse @ W_dec^T -----------
__global__ __launch_bounds__(256)
void decode_kernel(float* __restrict__ recon) {
    const int row = blockIdx.x;
    const int tid = threadIdx.x;
    __shared__ float sv[TOPK];
    __shared__ int   si[TOPK];
    if (tid < TOPK) {
        sv[tid] = g_vals[row * TOPK + tid];
        si[tid] = g_idx [row * TOPK + tid];
    }
    __syncthreads();

    float a0 = 0.0f, a1 = 0.0f, a2 = 0.0f;
    #pragma unroll
    for (int j = 0; j < TOPK; j++) {
        const float* wr = g_Wt + (size_t)si[j] * D_IN;
        float s = sv[j];
        a0 = fmaf(s, wr[tid],       a0);
        a1 = fmaf(s, wr[tid + 256], a1);
        a2 = fmaf(s, wr[tid + 512], a2);
    }
    size_t off = (size_t)row * D_IN + tid;
    recon[off]       = a0;
    recon[off + 256] = a1;
    recon[off + 512] = a2;
}

// ---------------- launch -----------------------------------------------------
extern "C" void kernel_launch(void* const* d_in, const int* in_sizes, int n_in,
                              void* d_out, int out_size) {
    const float* x    = (const float*)d_in[0];   // [8192, 768]
    const float* Wenc = (const float*)d_in[1];   // [16384, 768]
    const float* Wdec = (const float*)d_in[2];   // [768, 16384]

    float* out    = (float*)d_out;
    float* latent = out;                                  // [8192, 16384]
    float* recon  = out + (size_t)N_ROWS * D_HID;         // [8192, 768]

    cudaFuncSetAttribute(screen_gemm_kernel,
                         cudaFuncAttributeMaxDynamicSharedMemorySize, GEMM_SMEM);

    __nv_bfloat16* sbp = nullptr;
    cudaGetSymbolAddress((void**)&sbp, g_sb);

    transpose_kernel<<<dim3(D_HID / 32, D_IN / 32), dim3(32, 8)>>>(Wdec);
    convert_x_kernel<<<(N_ROWS * D_IN / 8) / 256, 256>>>(x);
    convert_w_kernel<<<(D_HID * D_IN / 8) / 256, 256>>>(Wenc);
    screen_gemm_kernel<<<dim3(D_HID / GBN, N_ROWS / GBM), 256, GEMM_SMEM>>>(sbp);
    candidate_kernel<<<N_ROWS, 512>>>(latent);
    rescore_kernel<<<N_ROWS, 256>>>(x, Wenc, latent);
    decode_kernel<<<N_ROWS, 256>>>(recon);
}